// round 1
// baseline (speedup 1.0000x reference)
#include <cuda_runtime.h>
#include <math.h>

// Problem constants
#define N_   256
#define T_   1000
#define NO_  10
#define NS_  10
#define HID_ 64
#define G3_  192   // 3*HID
#define D_   20    // NO+NS

// Scratch: hidden states [N,T,64] and global double accumulator.
__device__ float  g_h[(size_t)N_ * T_ * HID_];
__device__ double g_acc;

__global__ void k_zero() { g_acc = 0.0; }

__device__ __forceinline__ float sigmoidf_(float x) {
    return 1.0f / (1.0f + __expf(-x));
}
__device__ __forceinline__ float tanhf_(float x) {
    x = fminf(fmaxf(x, -15.0f), 15.0f);
    float e = __expf(2.0f * x);
    return (e - 1.0f) / (e + 1.0f);
}
__device__ __forceinline__ float softplusf_(float x) {
    // log1p(exp(x)), stable
    float ax = fabsf(x);
    return fmaxf(x, 0.0f) + log1pf(__expf(-ax));
}

// ---------------------------------------------------------------------------
// Kernel 1: persistent GRU. One CTA per sample, one thread per gate unit.
// Wh column (64) + Wi column (20) in registers; h broadcast via shared.
// Streams h_t to g_h. Input x_t prefetched 2 steps ahead via registers.
// ---------------------------------------------------------------------------
__global__ void __launch_bounds__(G3_, 2) k_gru(
    const float* __restrict__ Yi, const float* __restrict__ Xh,
    const float* __restrict__ Wi, const float* __restrict__ Wh,
    const float* __restrict__ bi, const float* __restrict__ bh)
{
    __shared__ __align__(16) float sh_h[HID_];
    __shared__ __align__(16) float sh_x[2][D_];
    __shared__ __align__(16) float sA[G3_];
    __shared__ __align__(16) float sB[HID_];

    const int j = threadIdx.x;
    const int n = blockIdx.x;

    float wi[D_], wh[HID_];
#pragma unroll
    for (int k = 0; k < D_; k++)   wi[k] = Wi[k * G3_ + j];
#pragma unroll
    for (int k = 0; k < HID_; k++) wh[k] = Wh[k * G3_ + j];
    const float bij = bi[j], bhj = bh[j];

    const float* yb = Yi + (size_t)n * T_ * NO_;
    const float* xb = Xh + (size_t)n * T_ * NS_;
    float*       hb = g_h + (size_t)n * T_ * HID_;

    float hreg = 0.0f;
    if (j < HID_) sh_h[j] = 0.0f;

    // Prologue: x_0 -> shared buf 0, x_1 -> prefetch register
    float xpre = 0.0f;
    if (j < NO_)      { sh_x[0][j] = yb[j];        xpre = yb[NO_ + j]; }
    else if (j < D_)  { sh_x[0][j] = xb[j - NO_];  xpre = xb[NS_ + (j - NO_)]; }
    __syncthreads();

    for (int t = 0; t < T_; t++) {
        // stage x_{t+1} into shared, prefetch x_{t+2}
        if (j < D_) {
            sh_x[(t + 1) & 1][j] = xpre;
            int tn = (t + 2 < T_) ? (t + 2) : (T_ - 1);
            xpre = (j < NO_) ? yb[tn * NO_ + j] : xb[tn * NS_ + (j - NO_)];
        }
        // phase A: g = bh + h@Wh col ; xp = bi + x@Wi col
        float g = bhj;
        const float4* h4 = (const float4*)sh_h;
#pragma unroll
        for (int k = 0; k < HID_ / 4; k++) {
            float4 hv = h4[k];
            g = fmaf(hv.x, wh[4 * k + 0], g);
            g = fmaf(hv.y, wh[4 * k + 1], g);
            g = fmaf(hv.z, wh[4 * k + 2], g);
            g = fmaf(hv.w, wh[4 * k + 3], g);
        }
        float xp = bij;
        const float4* x4 = (const float4*)sh_x[t & 1];
#pragma unroll
        for (int k = 0; k < D_ / 4; k++) {
            float4 xv = x4[k];
            xp = fmaf(xv.x, wi[4 * k + 0], xp);
            xp = fmaf(xv.y, wi[4 * k + 1], xp);
            xp = fmaf(xv.z, wi[4 * k + 2], xp);
            xp = fmaf(xv.w, wi[4 * k + 3], xp);
        }
        // r,z gates: combined preact. n gate: keep x-part and h-part separate.
        if (j < 2 * HID_) { sA[j] = xp + g; }
        else              { sA[j] = xp; sB[j - 2 * HID_] = g; }
        __syncthreads();

        // phase B: threads 0..63 finalize h
        if (j < HID_) {
            float r  = sigmoidf_(sA[j]);
            float z  = sigmoidf_(sA[j + HID_]);
            float nn = tanhf_(sA[j + 2 * HID_] + r * sB[j]);
            hreg = (1.0f - z) * nn + z * hreg;
            sh_h[j] = hreg;
            hb[t * HID_ + j] = hreg;   // stream state to global
        }
        __syncthreads();
    }
}

// ---------------------------------------------------------------------------
// Kernel 2: per-(n,t) log-likelihood. One thread per (n,t).
// mu = h@W_mu + b_mu ; var = softplus(h@W_var + b_var)
// L = H diag(var) H^T + Cw_n ; chol; logdet + ||L^{-1} e||^2
// ---------------------------------------------------------------------------
__global__ void __launch_bounds__(256) k_loglik(
    const float* __restrict__ Yi,
    const float* __restrict__ Cw,
    const float* __restrict__ H,
    const float* __restrict__ mu_w,
    const float* __restrict__ W_mu, const float* __restrict__ b_mu,
    const float* __restrict__ W_var, const float* __restrict__ b_var)
{
    __shared__ __align__(16) float sW[HID_ * 2 * NO_]; // [k][2q+s]: s=0 mu, s=1 var
    __shared__ float sH[NO_ * NS_];
    __shared__ float smw[NO_], sbm[NO_], sbv[NO_];
    __shared__ double sred[8];

    const int tid = threadIdx.x;
    for (int i = tid; i < HID_ * 2 * NO_; i += 256) {
        int k = i / (2 * NO_);
        int rr = i - k * 2 * NO_;
        int q = rr >> 1;
        sW[i] = (rr & 1) ? W_var[k * NO_ + q] : W_mu[k * NO_ + q];
    }
    if (tid < NO_ * NS_) sH[tid] = H[tid];
    if (tid < NO_) { smw[tid] = mu_w[tid]; sbm[tid] = b_mu[tid]; sbv[tid] = b_var[tid]; }
    __syncthreads();

    const int gid = blockIdx.x * 256 + tid;   // 0 .. N*T-1
    const int n   = gid / T_;
    const float* hp = g_h + (size_t)gid * HID_;

    float mu[NO_], vr[NO_];
#pragma unroll
    for (int q = 0; q < NO_; q++) { mu[q] = sbm[q]; vr[q] = sbv[q]; }

    const float4* hp4 = (const float4*)hp;
#pragma unroll
    for (int k4 = 0; k4 < HID_ / 4; k4++) {
        float4 hv = hp4[k4];
        float hx[4] = { hv.x, hv.y, hv.z, hv.w };
#pragma unroll
        for (int u = 0; u < 4; u++) {
            const float4* w4 = (const float4*)&sW[(4 * k4 + u) * 2 * NO_];
#pragma unroll
            for (int q2 = 0; q2 < NO_ / 2; q2++) {
                float4 w = w4[q2];
                mu[2 * q2]     = fmaf(hx[u], w.x, mu[2 * q2]);
                vr[2 * q2]     = fmaf(hx[u], w.y, vr[2 * q2]);
                mu[2 * q2 + 1] = fmaf(hx[u], w.z, mu[2 * q2 + 1]);
                vr[2 * q2 + 1] = fmaf(hx[u], w.w, vr[2 * q2 + 1]);
            }
        }
    }
    float va[NO_];
#pragma unroll
    for (int q = 0; q < NO_; q++) va[q] = softplusf_(vr[q]);

    // e = y - (H mu + mu_w)
    const float* yp = Yi + (size_t)gid * NO_;
    float ee[NO_];
#pragma unroll
    for (int i = 0; i < NO_; i++) {
        float m = smw[i];
#pragma unroll
        for (int jq = 0; jq < NS_; jq++) m = fmaf(sH[i * NS_ + jq], mu[jq], m);
        ee[i] = yp[i] - m;
    }

    // A (lower) = H diag(va) H^T + Cw_n
    const float* cwp = Cw + (size_t)n * NO_ * NO_;
    float A[55];
#pragma unroll
    for (int i = 0; i < NO_; i++) {
        float hvi[NS_];
#pragma unroll
        for (int jq = 0; jq < NS_; jq++) hvi[jq] = sH[i * NS_ + jq] * va[jq];
#pragma unroll
        for (int k = 0; k <= i; k++) {
            float s = cwp[i * NO_ + k];
#pragma unroll
            for (int jq = 0; jq < NS_; jq++) s = fmaf(hvi[jq], sH[k * NS_ + jq], s);
            A[i * (i + 1) / 2 + k] = s;
        }
    }

    // In-place Cholesky; logdet accumulated as sum log(d^2)
    float dinv[NO_];
    float logdet = 0.0f;
#pragma unroll
    for (int k = 0; k < NO_; k++) {
        float s = A[k * (k + 1) / 2 + k];
#pragma unroll
        for (int jq = 0; jq < k; jq++) {
            float l = A[k * (k + 1) / 2 + jq];
            s = fmaf(-l, l, s);
        }
        logdet += logf(s);
        float d = sqrtf(s);
        float di = 1.0f / d;
        dinv[k] = di;
#pragma unroll
        for (int i = k + 1; i < NO_; i++) {
            float s2 = A[i * (i + 1) / 2 + k];
#pragma unroll
            for (int jq = 0; jq < k; jq++)
                s2 = fmaf(-A[i * (i + 1) / 2 + jq], A[k * (k + 1) / 2 + jq], s2);
            A[i * (i + 1) / 2 + k] = s2 * di;
        }
    }

    // quad = || L^{-1} e ||^2 (forward solve only)
    float quad = 0.0f;
#pragma unroll
    for (int i = 0; i < NO_; i++) {
        float s = ee[i];
#pragma unroll
        for (int jq = 0; jq < i; jq++) s = fmaf(-A[i * (i + 1) / 2 + jq], ee[jq], s);
        s *= dinv[i];
        ee[i] = s;
        quad = fmaf(s, s, quad);
    }

    double local = (double)logdet + (double)quad;
#pragma unroll
    for (int o = 16; o > 0; o >>= 1)
        local += __shfl_down_sync(0xffffffffu, local, o);
    if ((tid & 31) == 0) sred[tid >> 5] = local;
    __syncthreads();
    if (tid == 0) {
        double s = 0.0;
#pragma unroll
        for (int w = 0; w < 8; w++) s += sred[w];
        atomicAdd(&g_acc, s);
    }
}

// ---------------------------------------------------------------------------
// Kernel 3: finalize scalar
// out = -0.5*log(2*pi) - 0.5 * S / (N*T*NO)
// ---------------------------------------------------------------------------
__global__ void k_fin(float* out) {
    out[0] = (float)(-0.91893853320467274178
                     - 0.5 * g_acc / ((double)N_ * (double)T_ * (double)NO_));
}

extern "C" void kernel_launch(void* const* d_in, const int* in_sizes, int n_in,
                              void* d_out, int out_size) {
    const float* Yi    = (const float*)d_in[0];
    const float* Xh    = (const float*)d_in[1];
    const float* Cw    = (const float*)d_in[2];
    const float* H     = (const float*)d_in[3];
    const float* mu_w  = (const float*)d_in[4];
    const float* Wi    = (const float*)d_in[5];
    const float* Wh    = (const float*)d_in[6];
    const float* bi    = (const float*)d_in[7];
    const float* bh    = (const float*)d_in[8];
    const float* W_mu  = (const float*)d_in[9];
    const float* b_mu  = (const float*)d_in[10];
    const float* W_var = (const float*)d_in[11];
    const float* b_var = (const float*)d_in[12];

    k_zero<<<1, 1>>>();
    k_gru<<<N_, G3_>>>(Yi, Xh, Wi, Wh, bi, bh);
    k_loglik<<<(N_ * T_) / 256, 256>>>(Yi, Cw, H, mu_w, W_mu, b_mu, W_var, b_var);
    k_fin<<<1, 1>>>((float*)d_out);
}

// round 3
// speedup vs baseline: 1.1432x; 1.1432x over previous
#include <cuda_runtime.h>
#include <math.h>

// Problem constants
#define N_   256
#define T_   1000
#define NO_  10
#define NS_  10
#define HID_ 64
#define G3_  192   // 3*HID
#define D_   20    // NO+NS
#define DP_  24    // D padded (multiple of 4 floats / 2 pairs)

// Scratch: hidden states [N,T,64] and global double accumulator.
__device__ float  g_h[(size_t)N_ * T_ * HID_];
__device__ double g_acc;

__global__ void k_zero() { g_acc = 0.0; }

// ---- packed f32x2 helpers (sm_103a; ptxas never auto-fuses these) ----
#define FMA2(d, a, b, c) \
    asm("fma.rn.f32x2 %0, %1, %2, %3;" : "=l"(d) : "l"(a), "l"(b), "l"(c))
#define ADD2(d, a, b) \
    asm("add.rn.f32x2 %0, %1, %2;" : "=l"(d) : "l"(a), "l"(b))
#define PACK2(d, lo, hi) \
    asm("mov.b64 %0, {%1, %2};" : "=l"(d) : "f"(lo), "f"(hi))
#define UNPACK2(lo, hi, s) \
    asm("mov.b64 {%0, %1}, %2;" : "=f"(lo), "=f"(hi) : "l"(s))

__device__ __forceinline__ float sigmoidf_(float x) {
    return 1.0f / (1.0f + __expf(-x));
}
__device__ __forceinline__ float tanhf_(float x) {
    x = fminf(fmaxf(x, -15.0f), 15.0f);
    float e = __expf(2.0f * x);
    return (e - 1.0f) / (e + 1.0f);
}
__device__ __forceinline__ float softplusf_(float x) {
    float ax = fabsf(x);
    return fmaxf(x, 0.0f) + log1pf(__expf(-ax));
}

// ---------------------------------------------------------------------------
// Kernel 1: persistent GRU. One CTA per sample, one thread per gate unit.
// f32x2 packed dot products; weights pre-packed into 64-bit register pairs.
// Thread roles: j in [0,64)=r-gate, [64,128)=z-gate, [128,192)=n-gate.
// ---------------------------------------------------------------------------
__global__ void __launch_bounds__(G3_, 2) k_gru(
    const float* __restrict__ Yi, const float* __restrict__ Xh,
    const float* __restrict__ Wi, const float* __restrict__ Wh,
    const float* __restrict__ bi, const float* __restrict__ bh)
{
    __shared__ __align__(16) float sh_h[HID_];
    __shared__ __align__(16) float sh_x[2][DP_];
    __shared__ __align__(16) float sRZ[2 * HID_];

    const int j = threadIdx.x;
    const int n = blockIdx.x;

    // ---- pack weights into f32x2 register pairs (loop-invariant) ----
    unsigned long long wh2[HID_ / 2];   // 32 pairs
    unsigned long long wi2[DP_ / 2];    // 12 pairs (zero-padded past D)
#pragma unroll
    for (int k = 0; k < HID_ / 2; k++) {
        float a = Wh[(2 * k) * G3_ + j];
        float b = Wh[(2 * k + 1) * G3_ + j];
        PACK2(wh2[k], a, b);
    }
#pragma unroll
    for (int k = 0; k < DP_ / 2; k++) {
        float a = (2 * k     < D_) ? Wi[(2 * k)     * G3_ + j] : 0.0f;
        float b = (2 * k + 1 < D_) ? Wi[(2 * k + 1) * G3_ + j] : 0.0f;
        PACK2(wi2[k], a, b);
    }
    const float bij = bi[j], bhj = bh[j];

    const float* yb = Yi + (size_t)n * T_ * NO_;
    const float* xb = Xh + (size_t)n * T_ * NS_;
    float*       hb = g_h + (size_t)n * T_ * HID_;

    float hreg = 0.0f;                 // owned by n-gate threads (j>=128)
    if (j < HID_) sh_h[j] = 0.0f;
    if (j >= D_ && j < DP_) { sh_x[0][j] = 0.0f; sh_x[1][j] = 0.0f; }

    // Prologue: x_0 -> shared buf 0, x_1 -> prefetch register
    float xpre = 0.0f;
    if (j < NO_)      { sh_x[0][j] = yb[j];        xpre = yb[NO_ + j]; }
    else if (j < D_)  { sh_x[0][j] = xb[j - NO_];  xpre = xb[NS_ + (j - NO_)]; }
    __syncthreads();

    for (int t = 0; t < T_; t++) {
        // stage x_{t+1} into shared, prefetch x_{t+2}
        if (j < D_) {
            sh_x[(t + 1) & 1][j] = xpre;
            int tn = (t + 2 < T_) ? (t + 2) : (T_ - 1);
            xpre = (j < NO_) ? yb[tn * NO_ + j] : xb[tn * NS_ + (j - NO_)];
        }

        // ---- phase A: packed dot products ----
        // Each ulonglong2 = 4 floats = 2 f32x2 pairs; HID_/4 = 16 chunks.
        unsigned long long acc0 = 0ull, acc1 = 0ull, acc2 = 0ull, acc3 = 0ull;
        const ulonglong2* h2 = (const ulonglong2*)sh_h;
#pragma unroll
        for (int k = 0; k < HID_ / 4; k++) {
            ulonglong2 hv = h2[k];
            if (k & 1) {
                FMA2(acc2, hv.x, wh2[2 * k],     acc2);
                FMA2(acc3, hv.y, wh2[2 * k + 1], acc3);
            } else {
                FMA2(acc0, hv.x, wh2[2 * k],     acc0);
                FMA2(acc1, hv.y, wh2[2 * k + 1], acc1);
            }
        }
        unsigned long long xa0 = 0ull, xa1 = 0ull;
        const ulonglong2* x2 = (const ulonglong2*)sh_x[t & 1];
#pragma unroll
        for (int k = 0; k < DP_ / 4; k++) {        // 6 chunks = 24 floats
            ulonglong2 xv = x2[k];
            FMA2(xa0, xv.x, wi2[2 * k],     xa0);
            FMA2(xa1, xv.y, wi2[2 * k + 1], xa1);
        }
        // reduce packed accumulators
        unsigned long long hs, hs01, hs23, xs;
        ADD2(hs01, acc0, acc1);
        ADD2(hs23, acc2, acc3);
        ADD2(hs, hs01, hs23);
        ADD2(xs, xa0, xa1);
        float hlo, hhi, xlo, xhi;
        UNPACK2(hlo, hhi, hs);
        UNPACK2(xlo, xhi, xs);
        float hacc = hlo + hhi;             // h @ Wh[:,j]
        float xacc = xlo + xhi;             // x @ Wi[:,j]

        if (j < 2 * HID_) {
            // r-gate (j<64) and z-gate (64<=j<128): sigmoid now, in parallel
            sRZ[j] = sigmoidf_(hacc + xacc + bij + bhj);
        }
        float xn = xacc + bij;              // only meaningful for j>=128
        float hn = hacc + bhj;
        __syncthreads();

        // ---- phase B: n-gate warps finalize h ----
        if (j >= 2 * HID_) {
            int u = j - 2 * HID_;
            float r = sRZ[u];
            float z = sRZ[u + HID_];
            float nn = tanhf_(xn + r * hn);
            hreg = fmaf(z, hreg - nn, nn);  // (1-z)*nn + z*h
            sh_h[u] = hreg;
            hb[t * HID_ + u] = hreg;
        }
        __syncthreads();
    }
}

// ---------------------------------------------------------------------------
// Kernel 2: per-(n,t) log-likelihood. One thread per (n,t).
// ---------------------------------------------------------------------------
__global__ void __launch_bounds__(256) k_loglik(
    const float* __restrict__ Yi,
    const float* __restrict__ Cw,
    const float* __restrict__ H,
    const float* __restrict__ mu_w,
    const float* __restrict__ W_mu, const float* __restrict__ b_mu,
    const float* __restrict__ W_var, const float* __restrict__ b_var)
{
    __shared__ __align__(16) float sW[HID_ * 2 * NO_]; // [k][2q+s]: s=0 mu, s=1 var
    __shared__ float sH[NO_ * NS_];
    __shared__ float smw[NO_], sbm[NO_], sbv[NO_];
    __shared__ double sred[8];

    const int tid = threadIdx.x;
    for (int i = tid; i < HID_ * 2 * NO_; i += 256) {
        int k = i / (2 * NO_);
        int rr = i - k * 2 * NO_;
        int q = rr >> 1;
        sW[i] = (rr & 1) ? W_var[k * NO_ + q] : W_mu[k * NO_ + q];
    }
    if (tid < NO_ * NS_) sH[tid] = H[tid];
    if (tid < NO_) { smw[tid] = mu_w[tid]; sbm[tid] = b_mu[tid]; sbv[tid] = b_var[tid]; }
    __syncthreads();

    const int gid = blockIdx.x * 256 + tid;   // 0 .. N*T-1
    const int n   = gid / T_;
    const float* hp = g_h + (size_t)gid * HID_;

    float mu[NO_], vr[NO_];
#pragma unroll
    for (int q = 0; q < NO_; q++) { mu[q] = sbm[q]; vr[q] = sbv[q]; }

    const float4* hp4 = (const float4*)hp;
#pragma unroll
    for (int k4 = 0; k4 < HID_ / 4; k4++) {
        float4 hv = hp4[k4];
        float hx[4] = { hv.x, hv.y, hv.z, hv.w };
#pragma unroll
        for (int u = 0; u < 4; u++) {
            const float4* w4 = (const float4*)&sW[(4 * k4 + u) * 2 * NO_];
#pragma unroll
            for (int q2 = 0; q2 < NO_ / 2; q2++) {
                float4 w = w4[q2];
                mu[2 * q2]     = fmaf(hx[u], w.x, mu[2 * q2]);
                vr[2 * q2]     = fmaf(hx[u], w.y, vr[2 * q2]);
                mu[2 * q2 + 1] = fmaf(hx[u], w.z, mu[2 * q2 + 1]);
                vr[2 * q2 + 1] = fmaf(hx[u], w.w, vr[2 * q2 + 1]);
            }
        }
    }
    float va[NO_];
#pragma unroll
    for (int q = 0; q < NO_; q++) va[q] = softplusf_(vr[q]);

    // e = y - (H mu + mu_w)
    const float* yp = Yi + (size_t)gid * NO_;
    float ee[NO_];
#pragma unroll
    for (int i = 0; i < NO_; i++) {
        float m = smw[i];
#pragma unroll
        for (int jq = 0; jq < NS_; jq++) m = fmaf(sH[i * NS_ + jq], mu[jq], m);
        ee[i] = yp[i] - m;
    }

    // A (lower) = H diag(va) H^T + Cw_n
    const float* cwp = Cw + (size_t)n * NO_ * NO_;
    float A[55];
#pragma unroll
    for (int i = 0; i < NO_; i++) {
        float hvi[NS_];
#pragma unroll
        for (int jq = 0; jq < NS_; jq++) hvi[jq] = sH[i * NS_ + jq] * va[jq];
#pragma unroll
        for (int k = 0; k <= i; k++) {
            float s = cwp[i * NO_ + k];
#pragma unroll
            for (int jq = 0; jq < NS_; jq++) s = fmaf(hvi[jq], sH[k * NS_ + jq], s);
            A[i * (i + 1) / 2 + k] = s;
        }
    }

    // In-place Cholesky; logdet accumulated as sum log(d^2)
    float dinv[NO_];
    float logdet = 0.0f;
#pragma unroll
    for (int k = 0; k < NO_; k++) {
        float s = A[k * (k + 1) / 2 + k];
#pragma unroll
        for (int jq = 0; jq < k; jq++) {
            float l = A[k * (k + 1) / 2 + jq];
            s = fmaf(-l, l, s);
        }
        logdet += logf(s);
        float d = sqrtf(s);
        float di = 1.0f / d;
        dinv[k] = di;
#pragma unroll
        for (int i = k + 1; i < NO_; i++) {
            float s2 = A[i * (i + 1) / 2 + k];
#pragma unroll
            for (int jq = 0; jq < k; jq++)
                s2 = fmaf(-A[i * (i + 1) / 2 + jq], A[k * (k + 1) / 2 + jq], s2);
            A[i * (i + 1) / 2 + k] = s2 * di;
        }
    }

    // quad = || L^{-1} e ||^2 (forward solve only)
    float quad = 0.0f;
#pragma unroll
    for (int i = 0; i < NO_; i++) {
        float s = ee[i];
#pragma unroll
        for (int jq = 0; jq < i; jq++) s = fmaf(-A[i * (i + 1) / 2 + jq], ee[jq], s);
        s *= dinv[i];
        ee[i] = s;
        quad = fmaf(s, s, quad);
    }

    double local = (double)logdet + (double)quad;
#pragma unroll
    for (int o = 16; o > 0; o >>= 1)
        local += __shfl_down_sync(0xffffffffu, local, o);
    if ((tid & 31) == 0) sred[tid >> 5] = local;
    __syncthreads();
    if (tid == 0) {
        double s = 0.0;
#pragma unroll
        for (int w = 0; w < 8; w++) s += sred[w];
        atomicAdd(&g_acc, s);
    }
}

// ---------------------------------------------------------------------------
// Kernel 3: finalize scalar
// ---------------------------------------------------------------------------
__global__ void k_fin(float* out) {
    out[0] = (float)(-0.91893853320467274178
                     - 0.5 * g_acc / ((double)N_ * (double)T_ * (double)NO_));
}

extern "C" void kernel_launch(void* const* d_in, const int* in_sizes, int n_in,
                              void* d_out, int out_size) {
    const float* Yi    = (const float*)d_in[0];
    const float* Xh    = (const float*)d_in[1];
    const float* Cw    = (const float*)d_in[2];
    const float* H     = (const float*)d_in[3];
    const float* mu_w  = (const float*)d_in[4];
    const float* Wi    = (const float*)d_in[5];
    const float* Wh    = (const float*)d_in[6];
    const float* bi    = (const float*)d_in[7];
    const float* bh    = (const float*)d_in[8];
    const float* W_mu  = (const float*)d_in[9];
    const float* b_mu  = (const float*)d_in[10];
    const float* W_var = (const float*)d_in[11];
    const float* b_var = (const float*)d_in[12];

    k_zero<<<1, 1>>>();
    k_gru<<<N_, G3_>>>(Yi, Xh, Wi, Wh, bi, bh);
    k_loglik<<<(N_ * T_) / 256, 256>>>(Yi, Cw, H, mu_w, W_mu, b_mu, W_var, b_var);
    k_fin<<<1, 1>>>((float*)d_out);
}